// round 13
// baseline (speedup 1.0000x reference)
#include <cuda_runtime.h>
#include <cstdint>

#define DD      512
#define HK      2048
#define NB      1024
#define LSLOTS  50
#define KSW     16           // split-K for W gemm
#define NBLK    256          // total blocks (4 supergroups x 64)
#define GRP     64           // blocks per supergroup
#define BD4     (NB * DD / 4)            // 131072 float4 per L-slot
#define N4ALL   (LSLOTS * NB * DD / 4)   // 6,553,600 float4

// Scratch (static device globals — no allocation)
__device__ float g_Wpart[KSW * DD * DD];     // split-K partials of Wt[j,a] (16 MB)
__device__ float g_W[DD * DD];               // Wt[j][a] = (wv@wo)[a][j]
__device__ float g_c[DD];                    // bv@wo + bo
__device__ float g_temp[NB * DD];            // 3w*(hid@W + c)

// per-supergroup monotone sync counters: [phase][J]
__device__ unsigned g_sync[2 * 4];

__device__ __forceinline__ void group_sync(int J, int phase) {
    __syncthreads();
    if (threadIdx.x == 0) {
        __threadfence();
        unsigned* c = &g_sync[phase * 4 + J];
        unsigned old = atomicAdd(c, 1u);
        unsigned target = (old / GRP + 1u) * GRP;
        while (*(volatile unsigned*)c < target) { __nanosleep(32); }
        __threadfence();
    }
    __syncthreads();
}

// ---------------------------------------------------------------------------
// helpers
// ---------------------------------------------------------------------------
__device__ __forceinline__ uint32_t f2tf(float x) {
    uint32_t r; asm("cvt.rna.tf32.f32 %0, %1;" : "=r"(r) : "f"(x)); return r;
}
__device__ __forceinline__ void mma8(float* d, const uint32_t* a, const uint32_t* b) {
    asm volatile(
        "mma.sync.aligned.m16n8k8.row.col.f32.tf32.tf32.f32 "
        "{%0,%1,%2,%3}, {%4,%5,%6,%7}, {%8,%9}, {%0,%1,%2,%3};"
        : "+f"(d[0]), "+f"(d[1]), "+f"(d[2]), "+f"(d[3])
        : "r"(a[0]), "r"(a[1]), "r"(a[2]), "r"(a[3]), "r"(b[0]), "r"(b[1]));
}

// ---------------------------------------------------------------------------
// P0 GEMM (R7/R11 layout): Wt partials, tile 128x128, Kc=32, double-buffered.
// ---------------------------------------------------------------------------
#define ASZ    4608
#define BSZ    4608
#define STAGE  (ASZ + BSZ)
#define SMEM_WORDS (2 * STAGE)           // 18432 words = 72 KB
#define SMEM_BYTES (SMEM_WORDS * 4)

template<int LDA, int LDB, int MTOT, int NTOT, int KCHUNK>
__device__ __forceinline__ void gemm_w_dev(const float* __restrict__ Ag,
                                           const float* __restrict__ Bg,
                                           float* __restrict__ C,
                                           uint32_t* smem,
                                           int bx, int by, int bz) {
    const int t = threadIdx.x;
    const int nBase = bx * 128;
    const int mBase = by * 128;
    const int kb    = bz * KCHUNK;

    const bool isA = (t < 128);
    const int tt = t & 127;
    const int rr = tt >> 3;
    const int fc = tt & 7;
    const int jq = tt & 31;
    const int kr = tt >> 5;

    constexpr int NS = KCHUNK / 32;
    float4 rg[8];

#define LDG(s)                                                                  \
    {                                                                           \
        if (isA) {                                                              \
            _Pragma("unroll")                                                   \
            for (int i = 0; i < 8; ++i)                                         \
                rg[i] = *(const float4*)&Ag[(size_t)(kb + (s)*32 + kr + 4*i) * LDA \
                                            + mBase + jq * 4];                  \
        } else {                                                                \
            _Pragma("unroll")                                                   \
            for (int i = 0; i < 8; ++i)                                         \
                rg[i] = *(const float4*)&Bg[(size_t)(nBase + rr + 16*i) * LDB   \
                                            + kb + (s)*32 + fc * 4];            \
        }                                                                       \
    }

    const int w = t >> 5, lane = t & 31;
    const int moff = (w & 3) * 32;
    const int noff = (w >> 2) * 64;
    const int g = lane >> 2, q = lane & 3;

    float acc[2][8][4];
#pragma unroll
    for (int mt = 0; mt < 2; mt++)
#pragma unroll
        for (int nt = 0; nt < 8; nt++)
#pragma unroll
            for (int r = 0; r < 4; r++) acc[mt][nt][r] = 0.0f;

    LDG(0);

    for (int s = 0; s < NS; ++s) {
        const int buf = s & 1;
        uint32_t* dst = smem + buf * STAGE + (isA ? 0 : ASZ);
        if (isA) {
#pragma unroll
            for (int i = 0; i < 8; ++i) {
                uint32_t* p = dst + (kr + 4 * i) * 132 + jq * 4;
                p[0] = f2tf(rg[i].x); p[1] = f2tf(rg[i].y);
                p[2] = f2tf(rg[i].z); p[3] = f2tf(rg[i].w);
            }
        } else {
#pragma unroll
            for (int i = 0; i < 8; ++i) {
                uint32_t* p = dst + (rr + 16 * i) * 36 + fc * 4;
                p[0] = f2tf(rg[i].x); p[1] = f2tf(rg[i].y);
                p[2] = f2tf(rg[i].z); p[3] = f2tf(rg[i].w);
            }
        }
        __syncthreads();
        if (s + 1 < NS) LDG(s + 1);

        const uint32_t* As = smem + buf * STAGE;
        const uint32_t* Bs = As + ASZ;
#pragma unroll
        for (int k0 = 0; k0 < 32; k0 += 8) {
            uint32_t af[2][4];
#pragma unroll
            for (int mt = 0; mt < 2; mt++) {
                const int m0 = moff + mt * 16 + g;
                af[mt][0] = As[(k0 + q) * 132 + m0];
                af[mt][1] = As[(k0 + q) * 132 + m0 + 8];
                af[mt][2] = As[(k0 + q + 4) * 132 + m0];
                af[mt][3] = As[(k0 + q + 4) * 132 + m0 + 8];
            }
            uint32_t bf[8][2];
#pragma unroll
            for (int nt = 0; nt < 8; nt++) {
                const int n0 = noff + nt * 8 + g;
                bf[nt][0] = Bs[n0 * 36 + k0 + q];
                bf[nt][1] = Bs[n0 * 36 + k0 + q + 4];
            }
#pragma unroll
            for (int mt = 0; mt < 2; mt++)
#pragma unroll
                for (int nt = 0; nt < 8; nt++)
                    mma8(acc[mt][nt], af[mt], bf[nt]);
        }
        __syncthreads();
    }
#undef LDG

    float* cz = C + (size_t)bz * MTOT * NTOT;
#pragma unroll
    for (int mt = 0; mt < 2; mt++) {
        const int r0 = mBase + moff + mt * 16 + g;
#pragma unroll
        for (int nt = 0; nt < 8; nt++) {
            const int c0 = nBase + noff + nt * 8 + q * 2;
            float2 v0 = make_float2(acc[mt][nt][0], acc[mt][nt][1]);
            float2 v1 = make_float2(acc[mt][nt][2], acc[mt][nt][3]);
            *(float2*)&cz[(size_t)r0 * NTOT + c0] = v0;
            *(float2*)&cz[(size_t)(r0 + 8) * NTOT + c0] = v1;
        }
    }
}

// ---------------------------------------------------------------------------
// Compute kernel, 256 blocks = 4 supergroups x 64, 2 blocks/SM.
// Supergroup J owns j-strip [128J, 128J+128):
//   P0 (4 a-tiles x 16 k-slices) | group sync | P1 reduce strip + bias |
//   group sync | P2' 64x32 temp tile (K=512) -> g_temp (scaled, with bias).
// ---------------------------------------------------------------------------
__global__ __launch_bounds__(256, 2) void k_compute(const float* __restrict__ wo,
                                                    const float* __restrict__ wv,
                                                    const float* __restrict__ hid,
                                                    const float* __restrict__ bv,
                                                    const float* __restrict__ bo,
                                                    const float* __restrict__ wsc) {
    extern __shared__ uint32_t smem[];
    __shared__ float sred[8];
    const int b = blockIdx.x;
    const int t = threadIdx.x;
    const int J = b >> 6;           // supergroup 0..3 (j-strip 128J..)
    const int u = b & 63;           // member within supergroup

    // ---- P0: Wt partials for rows [128J, 128J+128)
    gemm_w_dev<DD, HK, DD, DD, HK / KSW>(wo, wv, g_Wpart, smem,
                                         u & 3, J, u >> 2);
    group_sync(J, 0);

    // ---- P1a: reduce this strip's W partials (16384 float4 / 64 blocks)
    {
        const float4* p = (const float4*)g_Wpart;
        int i = J * 16384 + u * 256 + t;
        float4 s = p[i];
#pragma unroll
        for (int k = 1; k < KSW; k++) {
            float4 v = p[k * (DD * DD / 4) + i];
            s.x += v.x; s.y += v.y; s.z += v.z; s.w += v.w;
        }
        ((float4*)g_W)[i] = s;
    }
    // ---- P1b: bias c[j] for this strip (2 j's per block)
    {
        const int jloc = t >> 7;               // 0..1
        const int j = J * 128 + u * 2 + jloc;
        const int tk = t & 127;
        float acc = 0.0f;
        const int k0 = tk * 16;
        for (int k = k0; k < k0 + 16; k++)
            acc += bv[k] * wo[(size_t)k * DD + j];
#pragma unroll
        for (int off = 16; off > 0; off >>= 1)
            acc += __shfl_down_sync(0xFFFFFFFFu, acc, off);
        if ((t & 31) == 0) sred[t >> 5] = acc;
        __syncthreads();
        if (t < 2)
            g_c[J * 128 + u * 2 + t] = sred[4 * t] + sred[4 * t + 1]
                                     + sred[4 * t + 2] + sred[4 * t + 3]
                                     + bo[J * 128 + u * 2 + t];
    }
    group_sync(J, 1);

    // ---- P2': temp tile (64 b-rows x 32 j-cols, full K=512) -> g_temp
    {
        const int mBase = (u & 15) * 64;
        const int nBase = J * 128 + (u >> 4) * 32;
        const int kq = t & 15, r0 = t >> 4;      // loader map
        const int w = t >> 5, lane = t & 31;
        const int moff = (w & 3) * 16;
        const int noff = (w >> 2) * 16;
        const int g = lane >> 2, q = lane & 3;

        constexpr int APITCH = 68;
        constexpr int BOFF = 64 * APITCH;                 // 4352
        constexpr int P2STAGE = BOFF + 32 * APITCH;       // 6528

        float acc[2][4];
#pragma unroll
        for (int nt = 0; nt < 2; nt++)
#pragma unroll
            for (int r = 0; r < 4; r++) acc[nt][r] = 0.0f;

        float4 ra[4], rb[2];

#define LDG2(s)                                                                 \
        {                                                                       \
            _Pragma("unroll")                                                   \
            for (int i = 0; i < 4; ++i)                                         \
                ra[i] = *(const float4*)&hid[(size_t)(mBase + r0 + 16*i) * DD   \
                                             + (s)*64 + kq * 4];                \
            _Pragma("unroll")                                                   \
            for (int i = 0; i < 2; ++i)                                         \
                rb[i] = *(const float4*)&g_W[(size_t)(nBase + r0 + 16*i) * DD   \
                                             + (s)*64 + kq * 4];                \
        }

        LDG2(0);
        for (int s = 0; s < 8; ++s) {
            const int buf = s & 1;
            uint32_t* dst = smem + buf * P2STAGE;
#pragma unroll
            for (int i = 0; i < 4; ++i) {
                uint32_t* p = dst + (r0 + 16 * i) * APITCH + kq * 4;
                p[0] = f2tf(ra[i].x); p[1] = f2tf(ra[i].y);
                p[2] = f2tf(ra[i].z); p[3] = f2tf(ra[i].w);
            }
#pragma unroll
            for (int i = 0; i < 2; ++i) {
                uint32_t* p = dst + BOFF + (r0 + 16 * i) * APITCH + kq * 4;
                p[0] = f2tf(rb[i].x); p[1] = f2tf(rb[i].y);
                p[2] = f2tf(rb[i].z); p[3] = f2tf(rb[i].w);
            }
            __syncthreads();
            if (s + 1 < 8) LDG2(s + 1);

            const uint32_t* As = smem + buf * P2STAGE;
            const uint32_t* Bs = As + BOFF;
#pragma unroll
            for (int k0 = 0; k0 < 64; k0 += 8) {
                uint32_t af[4];
                const int m0 = moff + g;
                af[0] = As[m0 * APITCH + k0 + q];
                af[1] = As[(m0 + 8) * APITCH + k0 + q];
                af[2] = As[m0 * APITCH + k0 + q + 4];
                af[3] = As[(m0 + 8) * APITCH + k0 + q + 4];
                uint32_t bf[2][2];
#pragma unroll
                for (int nt = 0; nt < 2; nt++) {
                    const int n0 = noff + nt * 8 + g;
                    bf[nt][0] = Bs[n0 * APITCH + k0 + q];
                    bf[nt][1] = Bs[n0 * APITCH + k0 + q + 4];
                }
                mma8(acc[0], af, bf[0]);
                mma8(acc[1], af, bf[1]);
            }
            __syncthreads();
        }
#undef LDG2

        // epilogue: g_temp[b, j] = sc * (acc + c[j]) directly from registers
        const float sc = 3.0f * wsc[0];
#pragma unroll
        for (int nt = 0; nt < 2; nt++) {
            const int c0 = nBase + noff + nt * 8 + q * 2;
            const float cv0 = g_c[c0];
            const float cv1 = g_c[c0 + 1];
            float2 v0 = make_float2(sc * (acc[nt][0] + cv0), sc * (acc[nt][1] + cv1));
            float2 v1 = make_float2(sc * (acc[nt][2] + cv0), sc * (acc[nt][3] + cv1));
            *(float2*)&g_temp[(size_t)(mBase + moff + g) * DD + c0] = v0;
            *(float2*)&g_temp[(size_t)(mBase + moff + g + 8) * DD + c0] = v1;
        }
    }
}

// ---------------------------------------------------------------------------
// out[l,b,d] = momery[l,b,d] + temp[b,d]   (6144 blocks, occ ~85%)
// ---------------------------------------------------------------------------
__global__ __launch_bounds__(256) void k_add(const float4* __restrict__ mom,
                                             float4* __restrict__ out, int n4) {
    const float4* tp = (const float4*)g_temp;
    int stride = gridDim.x * blockDim.x;
    for (int i = blockIdx.x * blockDim.x + threadIdx.x; i < n4; i += stride) {
        float4 m = mom[i];
        float4 tv = tp[i & (BD4 - 1)];
        m.x += tv.x; m.y += tv.y; m.z += tv.z; m.w += tv.w;
        __stcs(&out[i], m);
    }
}

// ---------------------------------------------------------------------------
// Launch. Inputs (metadata order):
// 0 momery, 1 hid, 2 text_polarity, 3 attribute_polarity, 4 w,
// 5 p_w1, 6 p_b1, 7 p_w2, 8 p_b2, 9 wq, 10 bq, 11 wk, 12 bk,
// 13 wv, 14 bv, 15 wo, 16 bo
// ---------------------------------------------------------------------------
extern "C" void kernel_launch(void* const* d_in, const int* in_sizes, int n_in,
                              void* d_out, int out_size) {
    const float* momery = (const float*)d_in[0];
    const float* hid    = (const float*)d_in[1];
    const float* w      = (const float*)d_in[4];
    const float* wv     = (const float*)d_in[13];
    const float* bv     = (const float*)d_in[14];
    const float* wo     = (const float*)d_in[15];
    const float* bo     = (const float*)d_in[16];
    float* out = (float*)d_out;

    cudaFuncSetAttribute(k_compute, cudaFuncAttributeMaxDynamicSharedMemorySize,
                         SMEM_BYTES);

    k_compute<<<NBLK, 256, SMEM_BYTES>>>(wo, wv, hid, bv, bo, w);

    k_add<<<6144, 256>>>((const float4*)momery, (float4*)out, N4ALL);
}

// round 14
// speedup vs baseline: 1.0049x; 1.0049x over previous
#include <cuda_runtime.h>
#include <cstdint>

#define DD      512
#define HK      2048
#define NB      1024
#define LSLOTS  50
#define KSW     16           // split-K for W gemm
#define NGROUP  4
#define GRP     74           // blocks per supergroup
#define NBLK    (NGROUP * GRP)           // 296 = 2 x 148 SMs
#define BD4     (NB * DD / 4)            // 131072 float4 per L-slot

// per-launch ticket consumption (jobs + GRP failed grabs)
#define P0_JOBS 64
#define P2_JOBS 64
#define P3_JOBS 320
#define P0_TICKS (P0_JOBS + GRP)   // 138
#define P2_TICKS (P2_JOBS + GRP)   // 138
#define P3_TICKS (P3_JOBS + GRP)   // 394

// Scratch (static device globals — no allocation)
__device__ float g_Wpart[KSW * DD * DD];     // split-K partials of Wt[j,a] (16 MB)
__device__ float g_W[DD * DD];               // Wt[j][a] = (wv@wo)[a][j]
__device__ float g_c[DD];                    // bv@wo + bo
__device__ float g_temp[NB * DD];            // 3w*(hid@W + c), 2 MB (L2-hot)

// monotone sync counters [phase][J] and ticket counters [phase][J]
__device__ unsigned g_sync[3][NGROUP];
__device__ unsigned g_tick[3][NGROUP];

__device__ __forceinline__ void group_sync(int J, int phase) {
    __syncthreads();
    if (threadIdx.x == 0) {
        __threadfence();
        unsigned* c = &g_sync[phase][J];
        unsigned old = atomicAdd(c, 1u);
        unsigned target = (old / GRP + 1u) * GRP;
        while (*(volatile unsigned*)c < target) { __nanosleep(32); }
        __threadfence();
    }
    __syncthreads();
}

// ---------------------------------------------------------------------------
// helpers
// ---------------------------------------------------------------------------
__device__ __forceinline__ uint32_t f2tf(float x) {
    uint32_t r; asm("cvt.rna.tf32.f32 %0, %1;" : "=r"(r) : "f"(x)); return r;
}
__device__ __forceinline__ void mma8(float* d, const uint32_t* a, const uint32_t* b) {
    asm volatile(
        "mma.sync.aligned.m16n8k8.row.col.f32.tf32.tf32.f32 "
        "{%0,%1,%2,%3}, {%4,%5,%6,%7}, {%8,%9}, {%0,%1,%2,%3};"
        : "+f"(d[0]), "+f"(d[1]), "+f"(d[2]), "+f"(d[3])
        : "r"(a[0]), "r"(a[1]), "r"(a[2]), "r"(a[3]), "r"(b[0]), "r"(b[1]));
}

// ---------------------------------------------------------------------------
// P0 GEMM: Wt partial tile 128x128, Kc=32 stages, double-buffered.
// ---------------------------------------------------------------------------
#define ASZ    4608
#define BSZ    4608
#define STAGE  (ASZ + BSZ)
#define SMEM_WORDS (2 * STAGE)           // 72 KB
#define SMEM_BYTES (SMEM_WORDS * 4)

template<int LDA, int LDB, int MTOT, int NTOT, int KCHUNK>
__device__ __forceinline__ void gemm_w_dev(const float* __restrict__ Ag,
                                           const float* __restrict__ Bg,
                                           float* __restrict__ C,
                                           uint32_t* smem,
                                           int bx, int by, int bz) {
    const int t = threadIdx.x;
    const int nBase = bx * 128;
    const int mBase = by * 128;
    const int kb    = bz * KCHUNK;

    const bool isA = (t < 128);
    const int tt = t & 127;
    const int rr = tt >> 3;
    const int fc = tt & 7;
    const int jq = tt & 31;
    const int kr = tt >> 5;

    constexpr int NS = KCHUNK / 32;
    float4 rg[8];

#define LDG(s)                                                                  \
    {                                                                           \
        if (isA) {                                                              \
            _Pragma("unroll")                                                   \
            for (int i = 0; i < 8; ++i)                                         \
                rg[i] = *(const float4*)&Ag[(size_t)(kb + (s)*32 + kr + 4*i) * LDA \
                                            + mBase + jq * 4];                  \
        } else {                                                                \
            _Pragma("unroll")                                                   \
            for (int i = 0; i < 8; ++i)                                         \
                rg[i] = *(const float4*)&Bg[(size_t)(nBase + rr + 16*i) * LDB   \
                                            + kb + (s)*32 + fc * 4];            \
        }                                                                       \
    }

    const int w = t >> 5, lane = t & 31;
    const int moff = (w & 3) * 32;
    const int noff = (w >> 2) * 64;
    const int g = lane >> 2, q = lane & 3;

    float acc[2][8][4];
#pragma unroll
    for (int mt = 0; mt < 2; mt++)
#pragma unroll
        for (int nt = 0; nt < 8; nt++)
#pragma unroll
            for (int r = 0; r < 4; r++) acc[mt][nt][r] = 0.0f;

    LDG(0);

    for (int s = 0; s < NS; ++s) {
        const int buf = s & 1;
        uint32_t* dst = smem + buf * STAGE + (isA ? 0 : ASZ);
        if (isA) {
#pragma unroll
            for (int i = 0; i < 8; ++i) {
                uint32_t* p = dst + (kr + 4 * i) * 132 + jq * 4;
                p[0] = f2tf(rg[i].x); p[1] = f2tf(rg[i].y);
                p[2] = f2tf(rg[i].z); p[3] = f2tf(rg[i].w);
            }
        } else {
#pragma unroll
            for (int i = 0; i < 8; ++i) {
                uint32_t* p = dst + (rr + 16 * i) * 36 + fc * 4;
                p[0] = f2tf(rg[i].x); p[1] = f2tf(rg[i].y);
                p[2] = f2tf(rg[i].z); p[3] = f2tf(rg[i].w);
            }
        }
        __syncthreads();
        if (s + 1 < NS) LDG(s + 1);

        const uint32_t* As = smem + buf * STAGE;
        const uint32_t* Bs = As + ASZ;
#pragma unroll
        for (int k0 = 0; k0 < 32; k0 += 8) {
            uint32_t af[2][4];
#pragma unroll
            for (int mt = 0; mt < 2; mt++) {
                const int m0 = moff + mt * 16 + g;
                af[mt][0] = As[(k0 + q) * 132 + m0];
                af[mt][1] = As[(k0 + q) * 132 + m0 + 8];
                af[mt][2] = As[(k0 + q + 4) * 132 + m0];
                af[mt][3] = As[(k0 + q + 4) * 132 + m0 + 8];
            }
            uint32_t bf[8][2];
#pragma unroll
            for (int nt = 0; nt < 8; nt++) {
                const int n0 = noff + nt * 8 + g;
                bf[nt][0] = Bs[n0 * 36 + k0 + q];
                bf[nt][1] = Bs[n0 * 36 + k0 + q + 4];
            }
#pragma unroll
            for (int mt = 0; mt < 2; mt++)
#pragma unroll
                for (int nt = 0; nt < 8; nt++)
                    mma8(acc[mt][nt], af[mt], bf[nt]);
        }
        __syncthreads();
    }
#undef LDG

    float* cz = C + (size_t)bz * MTOT * NTOT;
#pragma unroll
    for (int mt = 0; mt < 2; mt++) {
        const int r0 = mBase + moff + mt * 16 + g;
#pragma unroll
        for (int nt = 0; nt < 8; nt++) {
            const int c0 = nBase + noff + nt * 8 + q * 2;
            float2 v0 = make_float2(acc[mt][nt][0], acc[mt][nt][1]);
            float2 v1 = make_float2(acc[mt][nt][2], acc[mt][nt][3]);
            *(float2*)&cz[(size_t)r0 * NTOT + c0] = v0;
            *(float2*)&cz[(size_t)(r0 + 8) * NTOT + c0] = v1;
        }
    }
}

// ---------------------------------------------------------------------------
// Mega-kernel, 296 blocks = 4 supergroups x 74, exactly 2 blocks/SM.
// Ticketed phases: P0 (64 W-tile jobs) | sync | P1 static reduce+bias | sync |
// P2 (64 temp-tile jobs -> g_temp) | sync | P3 (320 stream jobs).
// Monotone tickets: per launch each phase consumes exactly jobs+GRP grabs.
// ---------------------------------------------------------------------------
__global__ __launch_bounds__(256, 2) void k_all(const float* __restrict__ wo,
                                                const float* __restrict__ wv,
                                                const float* __restrict__ hid,
                                                const float* __restrict__ bv,
                                                const float* __restrict__ bo,
                                                const float* __restrict__ wsc,
                                                const float4* __restrict__ mom,
                                                float4* __restrict__ out) {
    extern __shared__ uint32_t smem[];
    __shared__ float sred[8];
    __shared__ int s_job;
    const int b = blockIdx.x;
    const int t = threadIdx.x;
    const int J = b / GRP;          // supergroup 0..3 (j-strip 128J..)
    const int u = b % GRP;          // member within supergroup

    // launch index from quiesced sync counter (updated only later this launch)
    const unsigned n = (*(volatile unsigned*)&g_sync[2][J]) / GRP;  // launches so far
    const unsigned base0 = n * P0_TICKS;
    const unsigned base2 = n * P2_TICKS;
    const unsigned base3 = n * P3_TICKS;

    // ---- P0: ticketed Wt partial tiles (64 jobs: a-tile = j&3, k-slice = j>>2)
    for (;;) {
        if (t == 0) s_job = (int)(atomicAdd(&g_tick[0][J], 1u) - base0);
        __syncthreads();
        const int job = s_job;
        __syncthreads();
        if (job >= P0_JOBS) break;
        gemm_w_dev<DD, HK, DD, DD, HK / KSW>(wo, wv, g_Wpart, smem,
                                             job & 3, J, job >> 2);
    }
    group_sync(J, 0);

    // ---- P1a: reduce this strip's W partials (16384 float4, blocks u<64)
    if (u < 64) {
        const float4* p = (const float4*)g_Wpart;
        int i = J * 16384 + u * 256 + t;
        float4 s = p[i];
#pragma unroll
        for (int k = 1; k < KSW; k++) {
            float4 v = p[k * (DD * DD / 4) + i];
            s.x += v.x; s.y += v.y; s.z += v.z; s.w += v.w;
        }
        ((float4*)g_W)[i] = s;

        // ---- P1b: bias c[j] for this strip (2 j's per block)
        const int jloc = t >> 7;               // 0..1
        const int j = J * 128 + u * 2 + jloc;
        const int tk = t & 127;
        float acc = 0.0f;
        const int k0 = tk * 16;
        for (int k = k0; k < k0 + 16; k++)
            acc += bv[k] * wo[(size_t)k * DD + j];
#pragma unroll
        for (int off = 16; off > 0; off >>= 1)
            acc += __shfl_down_sync(0xFFFFFFFFu, acc, off);
        if ((t & 31) == 0) sred[t >> 5] = acc;
        __syncthreads();
        if (t < 2)
            g_c[J * 128 + u * 2 + t] = sred[4 * t] + sred[4 * t + 1]
                                     + sred[4 * t + 2] + sred[4 * t + 3]
                                     + bo[J * 128 + u * 2 + t];
    }
    group_sync(J, 1);

    // ---- P2: ticketed temp tiles (64 jobs: 64 b-rows x 32 j-cols, K=512)
    {
        const int kq = t & 15, r0 = t >> 4;      // loader map
        const int w = t >> 5, lane = t & 31;
        const int moff = (w & 3) * 16;
        const int noff = (w >> 2) * 16;
        const int g = lane >> 2, q = lane & 3;

        constexpr int APITCH = 68;
        constexpr int BOFF = 64 * APITCH;                 // 4352
        constexpr int P2STAGE = BOFF + 32 * APITCH;       // 6528

        for (;;) {
            if (t == 0) s_job = (int)(atomicAdd(&g_tick[1][J], 1u) - base2);
            __syncthreads();
            const int job = s_job;
            __syncthreads();
            if (job >= P2_JOBS) break;

            const int mBase = (job & 15) * 64;
            const int nBase = J * 128 + (job >> 4) * 32;

            float acc[2][4];
#pragma unroll
            for (int nt = 0; nt < 2; nt++)
#pragma unroll
                for (int r = 0; r < 4; r++) acc[nt][r] = 0.0f;

            float4 ra[4], rb[2];

#define LDG2(s)                                                                 \
            {                                                                   \
                _Pragma("unroll")                                               \
                for (int i = 0; i < 4; ++i)                                     \
                    ra[i] = *(const float4*)&hid[(size_t)(mBase + r0 + 16*i) * DD \
                                                 + (s)*64 + kq * 4];            \
                _Pragma("unroll")                                               \
                for (int i = 0; i < 2; ++i)                                     \
                    rb[i] = *(const float4*)&g_W[(size_t)(nBase + r0 + 16*i) * DD \
                                                 + (s)*64 + kq * 4];            \
            }

            LDG2(0);
            for (int s = 0; s < 8; ++s) {
                const int buf = s & 1;
                uint32_t* dst = smem + buf * P2STAGE;
#pragma unroll
                for (int i = 0; i < 4; ++i) {
                    uint32_t* p = dst + (r0 + 16 * i) * APITCH + kq * 4;
                    p[0] = f2tf(ra[i].x); p[1] = f2tf(ra[i].y);
                    p[2] = f2tf(ra[i].z); p[3] = f2tf(ra[i].w);
                }
#pragma unroll
                for (int i = 0; i < 2; ++i) {
                    uint32_t* p = dst + BOFF + (r0 + 16 * i) * APITCH + kq * 4;
                    p[0] = f2tf(rb[i].x); p[1] = f2tf(rb[i].y);
                    p[2] = f2tf(rb[i].z); p[3] = f2tf(rb[i].w);
                }
                __syncthreads();
                if (s + 1 < 8) LDG2(s + 1);

                const uint32_t* As = smem + buf * P2STAGE;
                const uint32_t* Bs = As + BOFF;
#pragma unroll
                for (int k0 = 0; k0 < 64; k0 += 8) {
                    uint32_t af[4];
                    const int m0 = moff + g;
                    af[0] = As[m0 * APITCH + k0 + q];
                    af[1] = As[(m0 + 8) * APITCH + k0 + q];
                    af[2] = As[m0 * APITCH + k0 + q + 4];
                    af[3] = As[(m0 + 8) * APITCH + k0 + q + 4];
                    uint32_t bf[2][2];
#pragma unroll
                    for (int nt = 0; nt < 2; nt++) {
                        const int n0 = noff + nt * 8 + g;
                        bf[nt][0] = Bs[n0 * APITCH + k0 + q];
                        bf[nt][1] = Bs[n0 * APITCH + k0 + q + 4];
                    }
                    mma8(acc[0], af, bf[0]);
                    mma8(acc[1], af, bf[1]);
                }
                __syncthreads();
            }
#undef LDG2

            // epilogue: g_temp[b, j] = sc * (acc + c[j])
            const float sc = 3.0f * wsc[0];
#pragma unroll
            for (int nt = 0; nt < 2; nt++) {
                const int c0 = nBase + noff + nt * 8 + q * 2;
                const float cv0 = g_c[c0];
                const float cv1 = g_c[c0 + 1];
                float2 v0 = make_float2(sc * (acc[nt][0] + cv0),
                                        sc * (acc[nt][1] + cv1));
                float2 v1 = make_float2(sc * (acc[nt][2] + cv0),
                                        sc * (acc[nt][3] + cv1));
                *(float2*)&g_temp[(size_t)(mBase + moff + g) * DD + c0] = v0;
                *(float2*)&g_temp[(size_t)(mBase + moff + g + 8) * DD + c0] = v1;
            }
        }
    }
    group_sync(J, 2);

    // ---- P3: ticketed stream (320 jobs: tile = j&63, slot-chunk = j>>6)
    {
        const int ri = t >> 3;          // 0..31 (rows ri, ri+32)
        const int jq2 = t & 7;          // float4 within 32-col row
        for (;;) {
            if (t == 0) s_job = (int)(atomicAdd(&g_tick[2][J], 1u) - base3);
            __syncthreads();
            const int job = s_job;
            __syncthreads();
            if (job >= P3_JOBS) break;

            const int tl = job & 63;
            const int ch = job >> 6;                 // 0..4 -> slots [10ch, 10ch+10)
            const int mBase = (tl & 15) * 64;
            const int nBase = J * 128 + (tl >> 4) * 32;

            const float4* tp = (const float4*)g_temp;
            const int nb4 = nBase >> 2;
            const int base0i = (mBase + ri) * (DD / 4) + nb4 + jq2;
            const int base1i = (mBase + ri + 32) * (DD / 4) + nb4 + jq2;
            float4 T0 = tp[base0i];
            float4 T1 = tp[base1i];

#pragma unroll
            for (int h = 0; h < 2; ++h) {
                const int l0 = ch * 10 + h * 5;
                float4 m[10];
                int idx[10];
#pragma unroll
                for (int v = 0; v < 5; ++v) {
                    idx[2 * v]     = (l0 + v) * BD4 + base0i;
                    idx[2 * v + 1] = (l0 + v) * BD4 + base1i;
                    m[2 * v]     = __ldcs(&mom[idx[2 * v]]);
                    m[2 * v + 1] = __ldcs(&mom[idx[2 * v + 1]]);
                }
#pragma unroll
                for (int v = 0; v < 5; ++v) {
                    m[2*v].x += T0.x; m[2*v].y += T0.y;
                    m[2*v].z += T0.z; m[2*v].w += T0.w;
                    m[2*v+1].x += T1.x; m[2*v+1].y += T1.y;
                    m[2*v+1].z += T1.z; m[2*v+1].w += T1.w;
                    __stcs(&out[idx[2 * v]], m[2 * v]);
                    __stcs(&out[idx[2 * v + 1]], m[2 * v + 1]);
                }
            }
        }
    }
}

// ---------------------------------------------------------------------------
// Launch. Inputs (metadata order):
// 0 momery, 1 hid, 2 text_polarity, 3 attribute_polarity, 4 w,
// 5 p_w1, 6 p_b1, 7 p_w2, 8 p_b2, 9 wq, 10 bq, 11 wk, 12 bk,
// 13 wv, 14 bv, 15 wo, 16 bo
// ---------------------------------------------------------------------------
extern "C" void kernel_launch(void* const* d_in, const int* in_sizes, int n_in,
                              void* d_out, int out_size) {
    const float* momery = (const float*)d_in[0];
    const float* hid    = (const float*)d_in[1];
    const float* w      = (const float*)d_in[4];
    const float* wv     = (const float*)d_in[13];
    const float* bv     = (const float*)d_in[14];
    const float* wo     = (const float*)d_in[15];
    const float* bo     = (const float*)d_in[16];
    float* out = (float*)d_out;

    cudaFuncSetAttribute(k_all, cudaFuncAttributeMaxDynamicSharedMemorySize,
                         SMEM_BYTES);

    k_all<<<NBLK, 256, SMEM_BYTES>>>(wo, wv, hid, bv, bo, w,
                                     (const float4*)momery, (float4*)out);
}

// round 15
// speedup vs baseline: 1.1230x; 1.1175x over previous
#include <cuda_runtime.h>
#include <cstdint>

#define DD      512
#define HK      2048
#define NB      1024
#define LSLOTS  50
#define KSW     16           // split-K for W gemm
#define NBLK    256          // total blocks (4 supergroups x 64)
#define GRP     64           // blocks per supergroup
#define BD4     (NB * DD / 4)            // 131072 float4 per L-slot

// Scratch (static device globals — no allocation)
__device__ float g_Wpart[KSW * DD * DD];     // split-K partials of Wt[j,a] (16 MB)
__device__ float g_W[DD * DD];               // Wt[j][a] = (wv@wo)[a][j]
__device__ float g_c[DD];                    // bv@wo + bo

// per-supergroup monotone sync counters: [phase][J]
__device__ unsigned g_sync[2 * 4];

__device__ __forceinline__ void group_sync(int J, int phase) {
    __syncthreads();
    if (threadIdx.x == 0) {
        __threadfence();
        unsigned* c = &g_sync[phase * 4 + J];
        unsigned old = atomicAdd(c, 1u);
        unsigned target = (old / GRP + 1u) * GRP;
        while (*(volatile unsigned*)c < target) { __nanosleep(32); }
        __threadfence();
    }
    __syncthreads();
}

// ---------------------------------------------------------------------------
// helpers
// ---------------------------------------------------------------------------
__device__ __forceinline__ uint32_t f2tf(float x) {
    uint32_t r; asm("cvt.rna.tf32.f32 %0, %1;" : "=r"(r) : "f"(x)); return r;
}
__device__ __forceinline__ void mma8(float* d, const uint32_t* a, const uint32_t* b) {
    asm volatile(
        "mma.sync.aligned.m16n8k8.row.col.f32.tf32.tf32.f32 "
        "{%0,%1,%2,%3}, {%4,%5,%6,%7}, {%8,%9}, {%0,%1,%2,%3};"
        : "+f"(d[0]), "+f"(d[1]), "+f"(d[2]), "+f"(d[3])
        : "r"(a[0]), "r"(a[1]), "r"(a[2]), "r"(a[3]), "r"(b[0]), "r"(b[1]));
}
// ldmatrix x4: four 8x8 b16 matrices (tf32 floats viewed as b16 pairs).
__device__ __forceinline__ void ldsm4(uint32_t* r, uint32_t addr) {
    asm volatile("ldmatrix.sync.aligned.m8n8.x4.shared.b16 {%0,%1,%2,%3}, [%4];"
                 : "=r"(r[0]), "=r"(r[1]), "=r"(r[2]), "=r"(r[3]) : "r"(addr));
}

// ---------------------------------------------------------------------------
// P0 GEMM: Wt partial tile 128x128, Kc=32 stages, double-buffered.
// A (wo, k-major ATR) scalar LDS; B (wv, n-major) via ldmatrix.
// ---------------------------------------------------------------------------
#define ASZ    4608
#define BSZ    4608
#define STAGE  (ASZ + BSZ)
#define SMEM_WORDS (2 * STAGE)           // 72 KB
#define SMEM_BYTES (SMEM_WORDS * 4)

template<int LDA, int LDB, int MTOT, int NTOT, int KCHUNK>
__device__ __forceinline__ void gemm_w_dev(const float* __restrict__ Ag,
                                           const float* __restrict__ Bg,
                                           float* __restrict__ C,
                                           uint32_t* smem,
                                           int bx, int by, int bz) {
    const int t = threadIdx.x;
    const uint32_t sbase = (uint32_t)__cvta_generic_to_shared(smem);
    const int nBase = bx * 128;
    const int mBase = by * 128;
    const int kb    = bz * KCHUNK;

    const bool isA = (t < 128);
    const int tt = t & 127;
    const int rr = tt >> 3;
    const int fc = tt & 7;
    const int jq = tt & 31;
    const int kr = tt >> 5;

    constexpr int NS = KCHUNK / 32;
    float4 rg[8];

#define LDG(s)                                                                  \
    {                                                                           \
        if (isA) {                                                              \
            _Pragma("unroll")                                                   \
            for (int i = 0; i < 8; ++i)                                         \
                rg[i] = *(const float4*)&Ag[(size_t)(kb + (s)*32 + kr + 4*i) * LDA \
                                            + mBase + jq * 4];                  \
        } else {                                                                \
            _Pragma("unroll")                                                   \
            for (int i = 0; i < 8; ++i)                                         \
                rg[i] = *(const float4*)&Bg[(size_t)(nBase + rr + 16*i) * LDB   \
                                            + kb + (s)*32 + fc * 4];            \
        }                                                                       \
    }

    const int w = t >> 5, lane = t & 31;
    const int moff = (w & 3) * 32;
    const int noff = (w >> 2) * 64;
    const int g = lane >> 2, q = lane & 3;

    // B-type ldmatrix lane address (rows: +8 at lanes 16-31; col: +4 floats at
    // lanes 8-15/24-31). Byte units.
    const uint32_t sB0 = sbase +
        (ASZ + (uint32_t)(noff + ((lane >> 4) & 1) * 8 + (lane & 7)) * 36
             + ((lane >> 3) & 1) * 4) * 4;

    float acc[2][8][4];
#pragma unroll
    for (int mt = 0; mt < 2; mt++)
#pragma unroll
        for (int nt = 0; nt < 8; nt++)
#pragma unroll
            for (int r = 0; r < 4; r++) acc[mt][nt][r] = 0.0f;

    LDG(0);

    for (int s = 0; s < NS; ++s) {
        const int buf = s & 1;
        uint32_t* dst = smem + buf * STAGE + (isA ? 0 : ASZ);
        if (isA) {
#pragma unroll
            for (int i = 0; i < 8; ++i) {
                uint32_t* p = dst + (kr + 4 * i) * 132 + jq * 4;
                p[0] = f2tf(rg[i].x); p[1] = f2tf(rg[i].y);
                p[2] = f2tf(rg[i].z); p[3] = f2tf(rg[i].w);
            }
        } else {
#pragma unroll
            for (int i = 0; i < 8; ++i) {
                uint32_t* p = dst + (rr + 16 * i) * 36 + fc * 4;
                p[0] = f2tf(rg[i].x); p[1] = f2tf(rg[i].y);
                p[2] = f2tf(rg[i].z); p[3] = f2tf(rg[i].w);
            }
        }
        __syncthreads();
        if (s + 1 < NS) LDG(s + 1);

        const uint32_t* As = smem + buf * STAGE;
        const uint32_t bBs = sB0 + (uint32_t)buf * STAGE * 4;
#pragma unroll
        for (int k0 = 0; k0 < 32; k0 += 8) {
            uint32_t af[2][4];
#pragma unroll
            for (int mt = 0; mt < 2; mt++) {
                const int m0 = moff + mt * 16 + g;
                af[mt][0] = As[(k0 + q) * 132 + m0];
                af[mt][1] = As[(k0 + q) * 132 + m0 + 8];
                af[mt][2] = As[(k0 + q + 4) * 132 + m0];
                af[mt][3] = As[(k0 + q + 4) * 132 + m0 + 8];
            }
            uint32_t bf[8][2];
#pragma unroll
            for (int p = 0; p < 4; p++) {
                uint32_t r[4];
                ldsm4(r, bBs + (uint32_t)(p * 16 * 36 + k0) * 4);
                bf[2 * p][0] = r[0];     bf[2 * p][1] = r[1];
                bf[2 * p + 1][0] = r[2]; bf[2 * p + 1][1] = r[3];
            }
#pragma unroll
            for (int mt = 0; mt < 2; mt++)
#pragma unroll
                for (int nt = 0; nt < 8; nt++)
                    mma8(acc[mt][nt], af[mt], bf[nt]);
        }
        __syncthreads();
    }
#undef LDG

    float* cz = C + (size_t)bz * MTOT * NTOT;
#pragma unroll
    for (int mt = 0; mt < 2; mt++) {
        const int r0 = mBase + moff + mt * 16 + g;
#pragma unroll
        for (int nt = 0; nt < 8; nt++) {
            const int c0 = nBase + noff + nt * 8 + q * 2;
            float2 v0 = make_float2(acc[mt][nt][0], acc[mt][nt][1]);
            float2 v1 = make_float2(acc[mt][nt][2], acc[mt][nt][3]);
            *(float2*)&cz[(size_t)r0 * NTOT + c0] = v0;
            *(float2*)&cz[(size_t)(r0 + 8) * NTOT + c0] = v1;
        }
    }
}

// ---------------------------------------------------------------------------
// Mega-kernel, 256 blocks = 4 supergroups x 64, 2 blocks/SM.
// Supergroup J owns j-strip [128J, 128J+128) end-to-end:
//   P0 (4 a-tiles x 16 k-slices) | group sync | P1 reduce strip + bias |
//   group sync | P2' 64x32 temp tile (K=512) -> smem -> stream 50 L-slots.
// ---------------------------------------------------------------------------
__global__ __launch_bounds__(256, 2) void k_all(const float* __restrict__ wo,
                                                const float* __restrict__ wv,
                                                const float* __restrict__ hid,
                                                const float* __restrict__ bv,
                                                const float* __restrict__ bo,
                                                const float* __restrict__ wsc,
                                                const float4* __restrict__ mom,
                                                float4* __restrict__ out) {
    extern __shared__ uint32_t smem[];
    __shared__ float sred[8];
    const int b = blockIdx.x;
    const int t = threadIdx.x;
    const int J = b >> 6;           // supergroup 0..3 (j-strip 128J..)
    const int u = b & 63;           // member within supergroup

    // ---- P0: Wt partials for rows [128J, 128J+128)
    gemm_w_dev<DD, HK, DD, DD, HK / KSW>(wo, wv, g_Wpart, smem,
                                         u & 3, J, u >> 2);
    group_sync(J, 0);

    // ---- P1a: reduce this strip's W partials (16384 float4 / 64 blocks)
    {
        const float4* p = (const float4*)g_Wpart;
        int i = J * 16384 + u * 256 + t;
        float4 s = p[i];
#pragma unroll
        for (int k = 1; k < KSW; k++) {
            float4 v = p[k * (DD * DD / 4) + i];
            s.x += v.x; s.y += v.y; s.z += v.z; s.w += v.w;
        }
        ((float4*)g_W)[i] = s;
    }
    // ---- P1b: bias c[j] for this strip (2 j's per block)
    {
        const int jloc = t >> 7;               // 0..1
        const int j = J * 128 + u * 2 + jloc;
        const int tk = t & 127;
        float acc = 0.0f;
        const int k0 = tk * 16;
        for (int k = k0; k < k0 + 16; k++)
            acc += bv[k] * wo[(size_t)k * DD + j];
#pragma unroll
        for (int off = 16; off > 0; off >>= 1)
            acc += __shfl_down_sync(0xFFFFFFFFu, acc, off);
        if ((t & 31) == 0) sred[t >> 5] = acc;
        __syncthreads();
        if (t < 2)
            g_c[J * 128 + u * 2 + t] = sred[4 * t] + sred[4 * t + 1]
                                     + sred[4 * t + 2] + sred[4 * t + 3]
                                     + bo[J * 128 + u * 2 + t];
    }
    group_sync(J, 1);

    // ---- P2': temp tile (64 b-rows x 32 j-cols, full K=512), then stream.
    {
        const uint32_t sbase = (uint32_t)__cvta_generic_to_shared(smem);
        const int mBase = (u & 15) * 64;
        const int nBase = J * 128 + (u >> 4) * 32;
        const int kq = t & 15, r0 = t >> 4;      // loader map
        const int w = t >> 5, lane = t & 31;
        const int moff = (w & 3) * 16;
        const int noff = (w >> 2) * 16;
        const int g = lane >> 2, q = lane & 3;

        constexpr int APITCH = 68;
        constexpr int BOFF = 64 * APITCH;                 // 4352
        constexpr int P2STAGE = BOFF + 32 * APITCH;       // 6528

        // ldmatrix lane addresses (byte units)
        // A-type: regs a0,a1,a2,a3 = (r0,c0),(r+8,c0),(r0,c4),(r+8,c4)
        const uint32_t aA0 = sbase +
            ((uint32_t)(moff + ((lane >> 3) & 1) * 8 + (lane & 7)) * APITCH
             + ((lane >> 4) & 1) * 4) * 4;
        // B-type: regs = (r0,c0),(r0,c4),(r+8,c0),(r+8,c4)
        const uint32_t bB0 = sbase +
            ((uint32_t)BOFF
             + (uint32_t)(noff + ((lane >> 4) & 1) * 8 + (lane & 7)) * APITCH
             + ((lane >> 3) & 1) * 4) * 4;

        float acc[2][4];
#pragma unroll
        for (int nt = 0; nt < 2; nt++)
#pragma unroll
            for (int r = 0; r < 4; r++) acc[nt][r] = 0.0f;

        float4 ra[4], rb[2];

#define LDG2(s)                                                                 \
        {                                                                       \
            _Pragma("unroll")                                                   \
            for (int i = 0; i < 4; ++i)                                         \
                ra[i] = *(const float4*)&hid[(size_t)(mBase + r0 + 16*i) * DD   \
                                             + (s)*64 + kq * 4];                \
            _Pragma("unroll")                                                   \
            for (int i = 0; i < 2; ++i)                                         \
                rb[i] = *(const float4*)&g_W[(size_t)(nBase + r0 + 16*i) * DD   \
                                             + (s)*64 + kq * 4];                \
        }

        LDG2(0);
        for (int s = 0; s < 8; ++s) {
            const int buf = s & 1;
            uint32_t* dst = smem + buf * P2STAGE;
#pragma unroll
            for (int i = 0; i < 4; ++i) {
                uint32_t* p = dst + (r0 + 16 * i) * APITCH + kq * 4;
                p[0] = f2tf(ra[i].x); p[1] = f2tf(ra[i].y);
                p[2] = f2tf(ra[i].z); p[3] = f2tf(ra[i].w);
            }
#pragma unroll
            for (int i = 0; i < 2; ++i) {
                uint32_t* p = dst + BOFF + (r0 + 16 * i) * APITCH + kq * 4;
                p[0] = f2tf(rb[i].x); p[1] = f2tf(rb[i].y);
                p[2] = f2tf(rb[i].z); p[3] = f2tf(rb[i].w);
            }
            __syncthreads();
            if (s + 1 < 8) LDG2(s + 1);

            const uint32_t aAs = aA0 + (uint32_t)buf * P2STAGE * 4;
            const uint32_t bBs = bB0 + (uint32_t)buf * P2STAGE * 4;
#pragma unroll
            for (int k0 = 0; k0 < 64; k0 += 8) {
                uint32_t af[4];
                ldsm4(af, aAs + (uint32_t)k0 * 4);
                uint32_t rbf[4];
                ldsm4(rbf, bBs + (uint32_t)k0 * 4);
                uint32_t bf[2][2];
                bf[0][0] = rbf[0]; bf[0][1] = rbf[1];
                bf[1][0] = rbf[2]; bf[1][1] = rbf[3];
                mma8(acc[0], af, bf[0]);
                mma8(acc[1], af, bf[1]);
            }
            __syncthreads();
        }
#undef LDG2

        // epilogue: temp tile (64x32) with bias+scale into smem [64][36]
        float* ts = (float*)smem;
        const float sc = 3.0f * wsc[0];
#pragma unroll
        for (int nt = 0; nt < 2; nt++) {
            const int c0 = noff + nt * 8 + q * 2;
            const float cv0 = g_c[nBase + c0];
            const float cv1 = g_c[nBase + c0 + 1];
            ts[(moff + g) * 36 + c0]     = sc * (acc[nt][0] + cv0);
            ts[(moff + g) * 36 + c0 + 1] = sc * (acc[nt][1] + cv1);
            ts[(moff + g + 8) * 36 + c0]     = sc * (acc[nt][2] + cv0);
            ts[(moff + g + 8) * 36 + c0 + 1] = sc * (acc[nt][3] + cv1);
        }
        __syncthreads();

        // stream: out[l, mBase..+64, nBase..+32] for l = 0..49
        const int ri = t >> 3;          // 0..31 (rows ri, ri+32)
        const int jq2 = t & 7;          // float4 within 32-col row
        float4 T0 = *(const float4*)&ts[ri * 36 + jq2 * 4];
        float4 T1 = *(const float4*)&ts[(ri + 32) * 36 + jq2 * 4];
        const int nb4 = nBase >> 2;
        const int base0 = (mBase + ri) * (DD / 4) + nb4 + jq2;
        const int base1 = (mBase + ri + 32) * (DD / 4) + nb4 + jq2;

#pragma unroll 1
        for (int l = 0; l < LSLOTS; l += 5) {
            float4 m[10];
            int idx[10];
#pragma unroll
            for (int v = 0; v < 5; ++v) {
                idx[2 * v]     = (l + v) * BD4 + base0;
                idx[2 * v + 1] = (l + v) * BD4 + base1;
                m[2 * v]     = __ldcs(&mom[idx[2 * v]]);
                m[2 * v + 1] = __ldcs(&mom[idx[2 * v + 1]]);
            }
#pragma unroll
            for (int v = 0; v < 5; ++v) {
                m[2*v].x += T0.x; m[2*v].y += T0.y; m[2*v].z += T0.z; m[2*v].w += T0.w;
                m[2*v+1].x += T1.x; m[2*v+1].y += T1.y; m[2*v+1].z += T1.z; m[2*v+1].w += T1.w;
                __stcs(&out[idx[2 * v]], m[2 * v]);
                __stcs(&out[idx[2 * v + 1]], m[2 * v + 1]);
            }
        }
    }
}

// ---------------------------------------------------------------------------
// Launch. Inputs (metadata order):
// 0 momery, 1 hid, 2 text_polarity, 3 attribute_polarity, 4 w,
// 5 p_w1, 6 p_b1, 7 p_w2, 8 p_b2, 9 wq, 10 bq, 11 wk, 12 bk,
// 13 wv, 14 bv, 15 wo, 16 bo
// ---------------------------------------------------------------------------
extern "C" void kernel_launch(void* const* d_in, const int* in_sizes, int n_in,
                              void* d_out, int out_size) {
    const float* momery = (const float*)d_in[0];
    const float* hid    = (const float*)d_in[1];
    const float* w      = (const float*)d_in[4];
    const float* wv     = (const float*)d_in[13];
    const float* bv     = (const float*)d_in[14];
    const float* wo     = (const float*)d_in[15];
    const float* bo     = (const float*)d_in[16];
    float* out = (float*)d_out;

    cudaFuncSetAttribute(k_all, cudaFuncAttributeMaxDynamicSharedMemorySize,
                         SMEM_BYTES);

    k_all<<<NBLK, 256, SMEM_BYTES>>>(wo, wv, hid, bv, bo, w,
                                     (const float4*)momery, (float4*)out);
}